// round 17
// baseline (speedup 1.0000x reference)
#include <cuda_runtime.h>
#include <cstdint>

// Problem constants
#define HOP     128
#define WINL    512
#define PADW    192
#define NB      32
#define NT      131072
#define NFRM    1024
#define NSTAGE  11

// Tiling: one warp per block, one frame per lane.
// Input: rows 0..27 staged in smem (lanes 0..23); lanes 24..31 use a
// predicated register/LDG quad stream. OLA: 32-slot smem ring with diagonal
// retirement. Window: 257-entry mirrored hann half-table.
// Cascade: stages paired (s, s+6) into f32x2 lanes (stage 11 = zero dummy) —
// the feed of pair k is exactly pair k-1 (no repacking), so each step is
// 12 FFMA2 + 1 pack instead of 22 scalar FFMA. Lanewise rn => bit-identical.
#define NFB     32
#define BLK_PER_B (NFRM / NFB)          // 32
#define SROWS   28                      // staged input rows
#define RTHRESH 24                      // lanes >= RTHRESH use the reg path
#define INSZ    (SROWS * (HOP + 1))     // 3612 floats
#define ACCSZ   (32 * (HOP + 1))        // 4128 floats
#define WSZ     257
#define SMEM_BYTES ((INSZ + ACCSZ + WSZ) * sizeof(float))   // 31988 B -> 7 blocks/SM

#define TWO_PI_OVER_WIN 0.012271846303085129f

typedef unsigned long long u64;

// ---- packed f32x2 primitives ----
#define PK2(D, LO, HI) \
    asm("mov.b64 %0, {%1, %2};" : "=l"(D) : "r"(__float_as_uint(LO)), "r"(__float_as_uint(HI)))
#define LO2F(F, S) { unsigned _a, _b;                                              \
    asm("mov.b64 {%0, %1}, %2;" : "=r"(_a), "=r"(_b) : "l"(S));                    \
    (F) = __uint_as_float(_a); (void)_b; }
#define HI2F(F, S) { unsigned _a, _b;                                              \
    asm("mov.b64 {%0, %1}, %2;" : "=r"(_a), "=r"(_b) : "l"(S));                    \
    (F) = __uint_as_float(_b); (void)_a; }
#define FMA2(D, A, B, C) \
    asm("fma.rn.f32x2 %0, %1, %2, %3;" : "=l"(D) : "l"(A), "l"(B), "l"(C))

__device__ __forceinline__ float hannw(int n) {
    return 0.5f - 0.5f * __cosf((float)n * TWO_PI_OVER_WIN);
}

// OLA normalization at padded global position P.
__device__ float norm_at(int P) {
    int f_hi = P >> 7; if (f_hi > NFRM - 1) f_hi = NFRM - 1;
    int f_lo = (P >= 384) ? ((P - 384) >> 7) : 0;
    float s = 0.f;
    for (int f = f_lo; f <= f_hi; ++f) s += hannw(P - (f << 7));
    return s;
}

__global__ void halo_zero_kernel(float* __restrict__ out) {
    int b   = blockIdx.y;
    int blk = blockIdx.x + 1;
    int u   = blk * (NFB * HOP) - PADW + (int)threadIdx.x;
    out[(size_t)b * NT + u] = 0.f;
}

// Paired cascade step. Pair k holds (y_k, y_{k+6}); SRC = step n-1 state,
// DST = step n-2 state (overwritten to step n). Feed of pair k (k>=1) is
// SRC pair k-1 = (y_{k-1}, y_{k+5}) — the exact stage inputs. Pair 0's feed
// is (x, y_5(n-1)) = one pack. Output tap: y_10 = hi(DST4).
#define CASCADE2(S, D, X) {                                           \
    float _y5; LO2F(_y5, S##5);                                        \
    u64 _f0; PK2(_f0, (X), _y5);                                       \
    u64 _i0, _i1, _i2, _i3, _i4, _i5;                                  \
    FMA2(_i0, A1_0, S##0, _f0);                                        \
    FMA2(_i1, A1_1, S##1, S##0);                                       \
    FMA2(_i2, A1_2, S##2, S##1);                                       \
    FMA2(_i3, A1_3, S##3, S##2);                                       \
    FMA2(_i4, A1_4, S##4, S##3);                                       \
    FMA2(_i5, A1_5, S##5, S##4);                                       \
    FMA2(D##0, A2_0, D##0, _i0);                                       \
    FMA2(D##1, A2_1, D##1, _i1);                                       \
    FMA2(D##2, A2_2, D##2, _i2);                                       \
    FMA2(D##3, A2_3, D##3, _i3);                                       \
    FMA2(D##4, A2_4, D##4, _i4);                                       \
    FMA2(D##5, A2_5, D##5, _i5); }

// Guarded + predicated quad load (only reg-path lanes issue wavefronts).
__device__ __forceinline__ float4 ld4p(const float* __restrict__ xp, int pos0,
                                       int k, bool pred) {
    int pos = pos0 + 4 * k;
    if (pred && (unsigned)k <= 127u && (unsigned)pos <= (unsigned)(NT - 4))
        return *(const float4*)(xp + 4 * k);
    return make_float4(0.f, 0.f, 0.f, 0.f);
}

// ---- Operand gather (all compile-time indices -> registers) ----
#define FILL_X(B) {                                                    \
    xin[0] = g * (regp ? x0   : ipt[0]);                               \
    xin[1] = g * (regp ? x1   : ipt[1]);                               \
    xin[2] = g * (regp ? c0.x : ipt[2]);                               \
    xin[3] = g * (regp ? c0.y : ipt[3]);                               \
    xin[4] = g * (regp ? c0.z : ipt[4]);                               \
    xin[5] = g * (regp ? c0.w : ipt[5]);                               \
    xin[6] = g * (regp ? c1.x : ipt[6 + (B)]);                         \
    xin[7] = g * (regp ? c1.y : ipt[7 + (B)]);                         \
    xin[8] = g * (regp ? c1.z : ipt[8 + (B)]);                         \
    xin[9] = g * (regp ? c1.w : ipt[9 + (B)]);                         \
    xin[10] = g * (regp ? c2.x : ipt[10 + (B)]);                       \
    xin[11] = g * (regp ? c2.y : ipt[11 + (B)]);                       \
    xin[12] = g * (regp ? c2.z : ipt[12 + (B)]);                       \
    xin[13] = g * (regp ? c2.w : ipt[13 + (B)]);                       \
    xin[14] = g * (regp ? c3.x : ipt[14 + (B)]);                       \
    xin[15] = g * (regp ? c3.y : ipt[15 + (B)]); }

// Chunk-3 m=7 drain: t = 506..521, inputs valid only for K < 6 (t < 512).
#define FILL_X_DRAIN() {                                               \
    xin[0] = g * (regp ? x0   : ipt[0]);                               \
    xin[1] = g * (regp ? x1   : ipt[1]);                               \
    xin[2] = g * (regp ? c0.x : ipt[2]);                               \
    xin[3] = g * (regp ? c0.y : ipt[3]);                               \
    xin[4] = g * (regp ? c0.z : ipt[4]);                               \
    xin[5] = g * (regp ? c0.w : ipt[5]);                               \
    _Pragma("unroll")                                                  \
    for (int k = 6; k < 16; ++k) xin[k] = 0.f; }

#define FILL_W_A()  { _Pragma("unroll") for (int k = 0; k < 16; ++k) wv[k] = wq[k]; }
#define FILL_W_D()  { _Pragma("unroll") for (int k = 0; k < 16; ++k) wv[k] = wq[15 - k]; }
#define FILL_A()    { _Pragma("unroll") for (int k = 0; k < 16; ++k) av[k] = apt[k]; }

// ---- Compute bursts: no loads inside ----
#define RUN2_ST(K) {                                                   \
    float _y;                                                          \
    CASCADE2(sa, sb, xin[(K)]);                                        \
    HI2F(_y, sb4); apt[(K)]     = _y * wv[(K)];                        \
    CASCADE2(sb, sa, xin[(K) + 1]);                                    \
    HI2F(_y, sa4); apt[(K) + 1] = _y * wv[(K) + 1]; }
#define RUN16_ST()                                                     \
    RUN2_ST(0) RUN2_ST(2) RUN2_ST(4) RUN2_ST(6)                        \
    RUN2_ST(8) RUN2_ST(10) RUN2_ST(12) RUN2_ST(14)

#define RUN2_ACC(K) {                                                  \
    float _y;                                                          \
    CASCADE2(sa, sb, xin[(K)]);                                        \
    HI2F(_y, sb4); apt[(K)]     = fmaf(_y, wv[(K)],     av[(K)]);      \
    CASCADE2(sb, sa, xin[(K) + 1]);                                    \
    HI2F(_y, sa4); apt[(K) + 1] = fmaf(_y, wv[(K) + 1], av[(K) + 1]); }
#define RUN16_ACC()                                                    \
    RUN2_ACC(0) RUN2_ACC(2) RUN2_ACC(4) RUN2_ACC(6)                    \
    RUN2_ACC(8) RUN2_ACC(10) RUN2_ACC(12) RUN2_ACC(14)

#define PREFETCH(KQ)                                                   \
    float4 n0 = ld4p(xp, pos0, (KQ),     regp);                        \
    float4 n1 = ld4p(xp, pos0, (KQ) + 1, regp);                        \
    float4 n2 = ld4p(xp, pos0, (KQ) + 2, regp);                        \
    float4 n3 = ld4p(xp, pos0, (KQ) + 3, regp);

#define ROTATE()                                                       \
    x0 = c3.z; x1 = c3.w; c0 = n0; c1 = n1; c2 = n2; c3 = n3;

// Retire ring slot C holding span row C, then recycle it (zeroed).
#define RETIRE_EARLY(C) {                                              \
    const int sb_ = 129 * (C);                                         \
    _Pragma("unroll")                                                  \
    for (int k2 = 0; k2 < 4; ++k2) {                                   \
        int j = tid + 32 * k2;                                         \
        float v = acc_s[sb_ + j];                                      \
        int p = 128 * (C) + j;                                         \
        int u = S0 + p - PADW;                                         \
        if (blk == 0) { if (u >= 0) outb[u] = v / norm_at(p); }        \
        else atomicAdd(outb + u, v * 0.5f);                            \
        acc_s[sb_ + j] = 0.f;                                          \
    } }

__global__ __launch_bounds__(NFB, 1) void synth_kernel(const float* __restrict__ ex,
                                                       const float* __restrict__ gain,
                                                       const float* __restrict__ bq,
                                                       float* __restrict__ out) {
    extern __shared__ float sm[];
    float* in_s  = sm;                 // 28 padded input rows
    float* acc_s = sm + INSZ;          // 32 padded ring slots
    float* win_s = sm + INSZ + ACCSZ;  // 257-entry hann half-table

    const int b   = blockIdx.y;
    const int blk = blockIdx.x;
    const int F0  = blk * NFB;
    const int S0  = F0 * HOP;
    const int tid = (int)threadIdx.x;
    const bool regp = (tid >= RTHRESH);
    const int inb = 129 * (regp ? (RTHRESH - 1) : tid);
    float* outb = out + (size_t)b * NT;

    const int   pos0 = S0 + tid * HOP - PADW;
    const float* xp  = ex + (size_t)b * NT + pos0;

    // ---- Phase A: stage input rows coalesced; window table. (No acc zeroing:
    // chunk 0 pure-stores all 128 entries of every ring slot.)
    {
        const float* exb = ex + (size_t)b * NT + (S0 - PADW);
        #pragma unroll 1
        for (int it = 0; it < SROWS; ++it) {
            int e   = it * 128 + tid * 4;
            int pos = S0 - PADW + e;
            float4 v = make_float4(0.f, 0.f, 0.f, 0.f);
            if ((unsigned)pos <= (unsigned)(NT - 4))
                v = *(const float4*)(exb + e);
            int o = 129 * it + tid * 4;
            in_s[o] = v.x; in_s[o+1] = v.y; in_s[o+2] = v.z; in_s[o+3] = v.w;
        }
        for (int i = tid; i < WSZ; i += NFB) win_s[i] = hannw(i);
    }

    // Reg-path prologue + initial rotation quads
    float4 q0 = ld4p(xp, pos0, 0, regp);
    float4 q1 = ld4p(xp, pos0, 1, regp);
    float4 q2 = ld4p(xp, pos0, 2, regp);
    float4 c0 = ld4p(xp, pos0, 3, regp);
    float4 c1 = ld4p(xp, pos0, 4, regp);
    float4 c2 = ld4p(xp, pos0, 5, regp);
    float4 c3 = ld4p(xp, pos0, 6, regp);

    // ---- Per-frame coefficients, negated, packed as (stage k, stage k+6).
    // Stage s coeffs live at bp[3s+1], bp[3s+2]; stage 11 is a zero dummy.
    const int f = F0 + tid;
    const float g = gain[b * NFRM + f];
    const float* bp = bq + (size_t)(b * NFRM + f) * (NSTAGE * 3);
    u64 A1_0, A1_1, A1_2, A1_3, A1_4, A1_5;
    u64 A2_0, A2_1, A2_2, A2_3, A2_4, A2_5;
    PK2(A1_0, -bp[1],  -bp[19]);  PK2(A2_0, -bp[2],  -bp[20]);
    PK2(A1_1, -bp[4],  -bp[22]);  PK2(A2_1, -bp[5],  -bp[23]);
    PK2(A1_2, -bp[7],  -bp[25]);  PK2(A2_2, -bp[8],  -bp[26]);
    PK2(A1_3, -bp[10], -bp[28]);  PK2(A2_3, -bp[11], -bp[29]);
    PK2(A1_4, -bp[13], -bp[31]);  PK2(A2_4, -bp[14], -bp[32]);
    PK2(A1_5, -bp[16], 0.0f);     PK2(A2_5, -bp[17], 0.0f);

    // Paired ping-pong filter state: pair k = (y_k, y_{k+6}), zero-init.
    u64 sa0 = 0, sa1 = 0, sa2 = 0, sa3 = 0, sa4 = 0, sa5 = 0;
    u64 sb0 = 0, sb1 = 0, sb2 = 0, sb3 = 0, sb4 = 0, sb5 = 0;

    // Operand arrays (all indices compile-time -> registers)
    float xin[16], wv[16], av[16];

    __syncwarp();   // staging + window visible

    // ---- Prologue: t = 0..9 fill the filter pipeline (no output)
    #define PX(QF, T) (g * (regp ? (QF) : in_s[inb + (T)]))
    CASCADE2(sa, sb, PX(q0.x, 0)); CASCADE2(sb, sa, PX(q0.y, 1));
    CASCADE2(sa, sb, PX(q0.z, 2)); CASCADE2(sb, sa, PX(q0.w, 3));
    CASCADE2(sa, sb, PX(q1.x, 4)); CASCADE2(sb, sa, PX(q1.y, 5));
    CASCADE2(sa, sb, PX(q1.z, 6)); CASCADE2(sb, sa, PX(q1.w, 7));
    CASCADE2(sa, sb, PX(q2.x, 8)); CASCADE2(sb, sa, PX(q2.y, 9));
    float x0 = q2.z, x1 = q2.w;        // reg-path carries: t = 10, 11

    // ---- Chunk 0 (ascending window, PURE STORES — first write of each slot)
    {
        const int accb = 129 * tid;
        #pragma unroll 1
        for (int m = 0; m < 7; ++m) {
            const float* ipt = in_s + inb + 10 + 16 * m;
            float*       apt = acc_s + accb + 16 * m;
            const float* wq  = win_s + 16 * m;
            PREFETCH(3 + 4 * (m + 1))
            FILL_X(0) FILL_W_A()
            ROTATE()
            RUN16_ST()
        }
        {   // m = 7 (input row-crossing at K>=6)
            const float* ipt = in_s + inb + 122;
            float*       apt = acc_s + accb + 112;
            const float* wq  = win_s + 112;
            PREFETCH(35)
            FILL_X(1) FILL_W_A()
            ROTATE()
            RUN16_ST()
        }
        __syncwarp();
        RETIRE_EARLY(0)
        __syncwarp();
    }

    // ---- Chunk 1 (ascending window, accumulate)
    {
        const int accb = 129 * ((tid + 1) & 31);
        #pragma unroll 1
        for (int m = 0; m < 7; ++m) {
            const float* ipt = in_s + inb + 139 + 16 * m;     // 128+10+c(1)
            float*       apt = acc_s + accb + 16 * m;
            const float* wq  = win_s + 128 + 16 * m;
            PREFETCH(35 + 4 * (m + 1))
            FILL_X(0) FILL_W_A() FILL_A()
            ROTATE()
            RUN16_ACC()
        }
        {   // m = 7
            const float* ipt = in_s + inb + 251;              // 128+122+1
            float*       apt = acc_s + accb + 112;
            const float* wq  = win_s + 240;
            PREFETCH(67)
            FILL_X(1) FILL_W_A() FILL_A()
            ROTATE()
            RUN16_ACC()
        }
        __syncwarp();
        RETIRE_EARLY(1)
        __syncwarp();
    }

    // ---- Chunks 2,3 (mirrored window: w(j) = win_s[512-j], accumulate)
    #pragma unroll 1
    for (int c = 2; c < 4; ++c) {
        const int accb = 129 * ((tid + c) & 31);
        #pragma unroll 1
        for (int m = 0; m < 7; ++m) {
            const float* ipt = in_s + inb + 128 * c + 10 + c + 16 * m;
            float*       apt = acc_s + accb + 16 * m;
            const float* wq  = win_s + (512 - 128 * c) - 16 * m - 15;
            PREFETCH(3 + 32 * c + 4 * (m + 1))
            FILL_X(0) FILL_W_D() FILL_A()
            ROTATE()
            RUN16_ACC()
        }
        if (c == 2) {   // m = 7, row-crossing bump
            const float* ipt = in_s + inb + 380;              // 256+122+2
            float*       apt = acc_s + accb + 112;
            const float* wq  = win_s + 256 - 112 - 15;        // 129
            PREFETCH(99)
            FILL_X(1) FILL_W_D() FILL_A()
            ROTATE()
            RUN16_ACC()
            __syncwarp();
            RETIRE_EARLY(2)
            __syncwarp();
        } else {        // c == 3, m = 7: drain (t = 506..521; x=0 for t>=512)
            const float* ipt = in_s + inb + 509;              // 384+122+3
            float*       apt = acc_s + accb + 112;
            const float* wq  = win_s + 128 - 112 - 15;        // 1
            FILL_X_DRAIN() FILL_W_D() FILL_A()
            RUN16_ACC()
            __syncwarp();
        }
    }

    // ---- Phase C: retire remaining rows 3..34.
    #pragma unroll 1
    for (int B = 3; B < 35; ++B) {
        const int sb_ = 129 * (B & 31);
        #pragma unroll
        for (int k2 = 0; k2 < 4; ++k2) {
            int j = tid + 32 * k2;
            float v = acc_s[sb_ + j];
            int p = 128 * B + j;
            int u = S0 + p - PADW;
            if (B < 32) {
                outb[u] = v * 0.5f;                        // interior, norm==2
            } else if (blk != BLK_PER_B - 1) {
                atomicAdd(outb + u, v * 0.5f);             // right halo
            } else {
                if (u < NT) outb[u] = v / norm_at(S0 + p); // batch right edge
            }
        }
    }
}

extern "C" void kernel_launch(void* const* d_in, const int* in_sizes, int n_in,
                              void* d_out, int out_size) {
    const float* ex   = (const float*)d_in[0];   // (32, 131072) f32
    const float* gain = (const float*)d_in[1];   // (32, 1024)   f32
    const float* bq   = (const float*)d_in[2];   // (32, 1024, 11, 3) f32
    float* out = (float*)d_out;                  // (32, 131072) f32

    cudaFuncSetAttribute(synth_kernel, cudaFuncAttributeMaxDynamicSharedMemorySize,
                         (int)SMEM_BYTES);

    halo_zero_kernel<<<dim3(BLK_PER_B - 1, NB), 384>>>(out);
    synth_kernel<<<dim3(BLK_PER_B, NB), NFB, SMEM_BYTES>>>(ex, gain, bq, out);
}